// round 14
// baseline (speedup 1.0000x reference)
#include <cuda_runtime.h>
#include <cuda_bf16.h>
#include <stdint.h>
#include <math.h>

#define B_ 128
#define T_ 64
#define F_ 2048
#define H_ 1024
#define M_ 512
#define G4_ 4096

typedef __nv_bfloat16 bf16;

// ---------------- fp32 scratch ---------------------------------------------
__device__ float g_V[B_ * T_ * H_];
__device__ float g_A1[(size_t)B_ * T_ * G4_];
__device__ float g_abd[B_ * T_];
__device__ float g_wsiv[H_], g_wshv[H_];
__device__ float g_bb;
__device__ float g_c1[B_ * H_], g_c2[B_ * H_];
__device__ float g_part[2][B_][B_];     // [parity][b][cta] gate partial dots

// ---------------- split-bf16 operands --------------------------------------
__device__ bf16 g_vidh[B_ * T_ * F_], g_vidl[B_ * T_ * F_];
__device__ bf16 g_Vh[B_ * T_ * H_],   g_Vl[B_ * T_ * H_];
__device__ bf16 g_Wemb_h[H_ * F_],    g_Wemb_l[H_ * F_];
__device__ bf16 g_Wih1_h[G4_ * H_],   g_Wih1_l[G4_ * H_];
__device__ bf16 g_Whh1_h[G4_ * H_],   g_Whh1_l[G4_ * H_];
__device__ bf16 g_Wih2_h[G4_ * H_],   g_Wih2_l[G4_ * H_];
__device__ bf16 g_Whh2_h[G4_ * H_],   g_Whh2_l[G4_ * H_];
__device__ bf16 g_h1h[2][B_ * H_],    g_h1l[2][B_ * H_];
__device__ bf16 g_h2h[2][B_ * H_],    g_h2l[2][B_ * H_];
__device__ bf16 g_x2h[2][B_ * H_],    g_x2l[2][B_ * H_];

__device__ __forceinline__ float sigf(float x) { return 1.0f / (1.0f + expf(-x)); }
__device__ __forceinline__ uint32_t pack_hi(float x, float y) {
    __nv_bfloat162 t; t.x = __float2bfloat16(x); t.y = __float2bfloat16(y);
    return *(uint32_t*)&t;
}
__device__ __forceinline__ uint32_t pack_lo(float x, float y) {
    bf16 hx = __float2bfloat16(x), hy = __float2bfloat16(y);
    __nv_bfloat162 t;
    t.x = __float2bfloat16(x - __bfloat162float(hx));
    t.y = __float2bfloat16(y - __bfloat162float(hy));
    return *(uint32_t*)&t;
}
__device__ __forceinline__ void mma16816(float& c0, float& c1, float& c2, float& c3,
                                         uint32_t a0, uint32_t a1, uint32_t a2, uint32_t a3,
                                         uint32_t b0, uint32_t b1) {
    asm volatile(
        "mma.sync.aligned.m16n8k16.row.col.f32.bf16.bf16.f32 "
        "{%0,%1,%2,%3},{%4,%5,%6,%7},{%8,%9},{%0,%1,%2,%3};"
        : "+f"(c0), "+f"(c1), "+f"(c2), "+f"(c3)
        : "r"(a0), "r"(a1), "r"(a2), "r"(a3), "r"(b0), "r"(b1));
}
__device__ __forceinline__ void ldsm_x4(uint32_t& r0, uint32_t& r1, uint32_t& r2, uint32_t& r3,
                                        uint32_t addr) {
    asm volatile("ldmatrix.sync.aligned.m8n8.x4.shared.b16 {%0,%1,%2,%3}, [%4];"
                 : "=r"(r0), "=r"(r1), "=r"(r2), "=r"(r3) : "r"(addr));
}
__device__ __forceinline__ uint32_t smem_to_u32(const void* p) {
    uint32_t a;
    asm("{ .reg .u64 t; cvta.to.shared.u64 t, %1; cvt.u32.u64 %0, t; }" : "=r"(a) : "l"(p));
    return a;
}
__device__ __forceinline__ void cpa16(uint32_t dst, const void* src) {
    asm volatile("cp.async.cg.shared.global [%0], [%1], 16;" :: "r"(dst), "l"(src));
}
#define CP_COMMIT() asm volatile("cp.async.commit_group;" ::: "memory")
#define CP_WAIT1()  asm volatile("cp.async.wait_group 1;" ::: "memory")
#define CP_WAIT0()  asm volatile("cp.async.wait_group 0;" ::: "memory")

// ---------------- fused split: all 6 fp32 tensors -> (hi,lo) bf16 -----------
#define SPLIT_TOTAL4 8912896
__global__ void k_split_all(const float* __restrict__ video, const float* __restrict__ W_embed,
                            const float* __restrict__ W_ih1, const float* __restrict__ W_hh1,
                            const float* __restrict__ W_ih2, const float* __restrict__ W_hh2) {
    long i = (long)blockIdx.x * 256 + threadIdx.x;
    const float* src; bf16 *h, *l; long j;
    if (i < 4194304L)       { src = video;   h = g_vidh;   l = g_vidl;   j = i; }
    else if (i < 4718592L)  { src = W_embed; h = g_Wemb_h; l = g_Wemb_l; j = i - 4194304L; }
    else if (i < 5767168L)  { src = W_ih1;   h = g_Wih1_h; l = g_Wih1_l; j = i - 4718592L; }
    else if (i < 6815744L)  { src = W_hh1;   h = g_Whh1_h; l = g_Whh1_l; j = i - 5767168L; }
    else if (i < 7864320L)  { src = W_ih2;   h = g_Wih2_h; l = g_Wih2_l; j = i - 6815744L; }
    else                    { src = W_hh2;   h = g_Whh2_h; l = g_Whh2_l; j = i - 7864320L; }
    float4 v = ((const float4*)src)[j];
    uint2 hp, lp;
    hp.x = pack_hi(v.x, v.y); hp.y = pack_hi(v.z, v.w);
    lp.x = pack_lo(v.x, v.y); lp.y = pack_lo(v.z, v.w);
    ((uint2*)h)[j] = hp;
    ((uint2*)l)[j] = lp;
}

// ---------------- boundary-detector projections ----------------------------
__global__ void k_proj(const float* __restrict__ Wsi, const float* __restrict__ Wsh,
                       const float* __restrict__ b_bd, const float* __restrict__ vs) {
    int blk = blockIdx.x;
    if (blk < 8) {
        int h = blk * 128 + threadIdx.x;
        float s1 = 0.f, s2 = 0.f;
        for (int m = 0; m < M_; m++) {
            float v = vs[m];
            s1 += Wsi[m * H_ + h] * v;
            s2 += Wsh[m * H_ + h] * v;
        }
        g_wsiv[h] = s1;
        g_wshv[h] = s2;
    } else {
        __shared__ float red[128];
        float s = 0.f;
        for (int m = threadIdx.x; m < M_; m += 128) s += b_bd[m] * vs[m];
        red[threadIdx.x] = s;
        __syncthreads();
        for (int st = 64; st > 0; st >>= 1) {
            if (threadIdx.x < st) red[threadIdx.x] += red[threadIdx.x + st];
            __syncthreads();
        }
        if (threadIdx.x == 0) g_bb = red[0];
    }
}

// ========== precompute GEMM: BM128 x BN128 x BK32, warp 64x32, cp.async =====
#define MM_TA    10240
#define MM_BUF   (4 * MM_TA)
#define MM_SMEM  (2 * MM_BUF)

__device__ __forceinline__ void mm_pf(uint32_t sb, int stage,
                                      const uint4* __restrict__ A4h, const uint4* __restrict__ A4l,
                                      const uint4* __restrict__ B4h, const uint4* __restrict__ B4l,
                                      int bm0, int bn0, int kq, int K8, int tid) {
    uint32_t st = sb + stage * MM_BUF;
#pragma unroll
    for (int rep = 0; rep < 2; rep++) {
        int u = tid + 256 * rep;
        int r = u >> 2, q = u & 3;
        uint32_t off = (uint32_t)(r * 80 + q * 16);
        cpa16(st + off,              A4h + (size_t)(bm0 + r) * K8 + kq + q);
        cpa16(st + MM_TA + off,      A4l + (size_t)(bm0 + r) * K8 + kq + q);
        cpa16(st + 2 * MM_TA + off,  B4h + (size_t)(bn0 + r) * K8 + kq + q);
        cpa16(st + 3 * MM_TA + off,  B4l + (size_t)(bn0 + r) * K8 + kq + q);
    }
}

__device__ __forceinline__ void mm_comp(uint32_t sb, int stage, uint32_t aOff, uint32_t bOff,
                                        float acc[4][4][4]) {
    uint32_t st = sb + stage * MM_BUF;
    uint32_t sAH = st, sAL = st + MM_TA, sBH = st + 2 * MM_TA, sBL = st + 3 * MM_TA;
#pragma unroll
    for (int ks = 0; ks < 32; ks += 16) {
        uint32_t kb = (uint32_t)(ks * 2);
        uint32_t bh[2][4], bl[2][4];
#pragma unroll
        for (int p = 0; p < 2; p++) {
            ldsm_x4(bh[p][0], bh[p][1], bh[p][2], bh[p][3], sBH + bOff + p * 1280 + kb);
            ldsm_x4(bl[p][0], bl[p][1], bl[p][2], bl[p][3], sBL + bOff + p * 1280 + kb);
        }
#pragma unroll
        for (int mt = 0; mt < 4; mt++) {
            uint32_t ah[4], al[4];
            ldsm_x4(ah[0], ah[1], ah[2], ah[3], sAH + aOff + mt * 1280 + kb);
            ldsm_x4(al[0], al[1], al[2], al[3], sAL + aOff + mt * 1280 + kb);
#pragma unroll
            for (int nt = 0; nt < 4; nt++) {
                int p = nt >> 1, j = nt & 1;
                float* d = acc[mt][nt];
                mma16816(d[0], d[1], d[2], d[3], ah[0], ah[1], ah[2], ah[3], bh[p][2 * j], bh[p][2 * j + 1]);
                mma16816(d[0], d[1], d[2], d[3], ah[0], ah[1], ah[2], ah[3], bl[p][2 * j], bl[p][2 * j + 1]);
                mma16816(d[0], d[1], d[2], d[3], al[0], al[1], al[2], al[3], bh[p][2 * j], bh[p][2 * j + 1]);
            }
        }
    }
}

template <bool RELU, bool BIAS, bool SPLIT>
__global__ void __launch_bounds__(256) mm_pre(const bf16* __restrict__ Ah, const bf16* __restrict__ Al,
                       const bf16* __restrict__ Bh, const bf16* __restrict__ Bl,
                       const float* __restrict__ bias, float* __restrict__ C,
                       bf16* __restrict__ Ch, bf16* __restrict__ Cl, int N, int K) {
    extern __shared__ char smp[];
    uint32_t sb = smem_to_u32(smp);
    int tid = threadIdx.x, lane = tid & 31, wid = tid >> 5;
    int wm = wid >> 2, wn = wid & 3;
    int gr = lane >> 2, tc = lane & 3;
    int bn0 = blockIdx.x * 128, bm0 = blockIdx.y * 128;
    int K8 = K >> 3;
    const uint4* A4h = (const uint4*)Ah; const uint4* A4l = (const uint4*)Al;
    const uint4* B4h = (const uint4*)Bh; const uint4* B4l = (const uint4*)Bl;

    uint32_t aOff = (uint32_t)((wm * 64 + (lane & 15)) * 80 + (lane >> 4) * 16);
    uint32_t bOff = (uint32_t)((wn * 32 + ((lane >> 4) & 1) * 8 + (lane & 7)) * 80
                               + ((lane >> 3) & 1) * 16);

    float acc[4][4][4];
#pragma unroll
    for (int a = 0; a < 4; a++)
#pragma unroll
        for (int b = 0; b < 4; b++)
#pragma unroll
            for (int c = 0; c < 4; c++) acc[a][b][c] = 0.f;

    int nc = K >> 5;
    mm_pf(sb, 0, A4h, A4l, B4h, B4l, bm0, bn0, 0, K8, tid);
    CP_COMMIT();
    for (int c = 0; c < nc; c++) {
        int stg = c & 1;
        if (c + 1 < nc) {
            mm_pf(sb, stg ^ 1, A4h, A4l, B4h, B4l, bm0, bn0, (c + 1) * 4, K8, tid);
            CP_COMMIT();
            CP_WAIT1();
        } else {
            CP_WAIT0();
        }
        __syncthreads();
        mm_comp(sb, stg, aOff, bOff, acc);
        __syncthreads();
    }

#pragma unroll
    for (int mt = 0; mt < 4; mt++)
#pragma unroll
        for (int nt = 0; nt < 4; nt++) {
            int row0 = bm0 + wm * 64 + mt * 16 + gr;
            int col = bn0 + wn * 32 + nt * 8 + 2 * tc;
            float2 bs = BIAS ? *(const float2*)&bias[col] : make_float2(0.f, 0.f);
#pragma unroll
            for (int rs = 0; rs < 2; rs++) {
                int row = row0 + 8 * rs;
                float v0 = acc[mt][nt][2 * rs] + bs.x;
                float v1 = acc[mt][nt][2 * rs + 1] + bs.y;
                if (RELU) { v0 = fmaxf(v0, 0.f); v1 = fmaxf(v1, 0.f); }
                *(float2*)&C[(size_t)row * N + col] = make_float2(v0, v1);
                if (SPLIT) {
                    *(uint32_t*)&Ch[(size_t)row * N + col] = pack_hi(v0, v1);
                    *(uint32_t*)&Cl[(size_t)row * N + col] = pack_lo(v0, v1);
                }
            }
        }
}

// ---------------- fused abd + state init + g_part zero ----------------------
__global__ void k_abd_init() {
    if (blockIdx.x < 1024) {
        int r = blockIdx.x * 8 + (threadIdx.x >> 5);
        int lane = threadIdx.x & 31;
        const float* vr = g_V + (size_t)r * H_;
        float s = 0.f;
        for (int h = lane; h < H_; h += 32) s += vr[h] * g_wsiv[h];
#pragma unroll
        for (int o = 16; o > 0; o >>= 1) s += __shfl_xor_sync(0xffffffffu, s, o);
        if (lane == 0) g_abd[r] = s + g_bb;
    } else if (blockIdx.x < 1536) {
        int i = (blockIdx.x - 1024) * 256 + threadIdx.x;
        if (i < B_ * H_) {
            g_c1[i] = 0.f; g_c2[i] = 0.f;
            bf16 z = __float2bfloat16(0.f);
            g_h1h[0][i] = z; g_h1l[0][i] = z;
            g_h2h[0][i] = z; g_h2l[0][i] = z;
        }
    } else {
        int i = (blockIdx.x - 1536) * 256 + threadIdx.x;
        if (i < B_ * B_) ((float*)g_part)[i] = 0.f;   // zero parity-0 partials
    }
}

// ================= fused scan step kernel ===================================
// PH bit0: lstm2(t-1) phase; PH bit1: lstm1(t) phase. grid = 128, 256 thr.
#define A_ST   136
#define A_TILE (128 * A_ST * 2)
#define B_TILE (32 * A_ST * 2)
#define BUF_SZ (2 * A_TILE + 2 * B_TILE)
#define SM_AH(b) ((b) * BUF_SZ)
#define SM_AL(b) ((b) * BUF_SZ + A_TILE)
#define SM_BH(b) ((b) * BUF_SZ + 2 * A_TILE)
#define SM_BL(b) ((b) * BUF_SZ + 2 * A_TILE + B_TILE)
#define SMEM_SCAN (2 * BUF_SZ)

__device__ __forceinline__ void pf_A(uint32_t sb, int buf,
                                     const uint4* __restrict__ Ah4,
                                     const uint4* __restrict__ Al4,
                                     int kq, int tid) {
#pragma unroll
    for (int rep = 0; rep < 8; rep++) {
        int u = tid + 256 * rep;
        int r = u >> 4, q = u & 15;
        uint32_t off = (uint32_t)(r * (A_ST * 2) + q * 16);
        cpa16(sb + SM_AH(buf) + off, Ah4 + (size_t)r * 128 + kq + q);
        cpa16(sb + SM_AL(buf) + off, Al4 + (size_t)r * 128 + kq + q);
    }
}
__device__ __forceinline__ void pf_B(uint32_t sb, int buf,
                                     const uint4* __restrict__ Wh4,
                                     const uint4* __restrict__ Wl4,
                                     int hb, int kq, int tid) {
#pragma unroll
    for (int rep = 0; rep < 2; rep++) {
        int u = tid + 256 * rep;
        int n = u >> 4, q = u & 15;
        int wr = (n >> 3) * H_ + hb + (n & 7);
        uint32_t off = (uint32_t)(n * (A_ST * 2) + q * 16);
        cpa16(sb + SM_BH(buf) + off, Wh4 + (size_t)wr * 128 + kq + q);
        cpa16(sb + SM_BL(buf) + off, Wl4 + (size_t)wr * 128 + kq + q);
    }
}
__device__ __forceinline__ void comp_chunk(uint32_t sb, int buf, int wid, int lane,
                                           float acc[4][4]) {
    uint32_t aOff = (uint32_t)((wid * 16 + (lane & 15)) * (A_ST * 2) + (lane >> 4) * 16);
    uint32_t ahB = sb + SM_AH(buf) + aOff;
    uint32_t alB = sb + SM_AL(buf) + aOff;
    uint32_t bRow = (uint32_t)(((lane >> 4) & 1) * 8 + (lane & 7));
    uint32_t bCol = (uint32_t)(((lane >> 3) & 1) * 16);
    uint32_t bOff01 = bRow * (A_ST * 2) + bCol;
    uint32_t bOff23 = (bRow + 16) * (A_ST * 2) + bCol;
    uint32_t bhB = sb + SM_BH(buf), blB = sb + SM_BL(buf);
#pragma unroll
    for (int ks = 0; ks < 128; ks += 16) {
        uint32_t kb = (uint32_t)(ks * 2);
        uint32_t ah[4], al[4], bh01[4], bh23[4], bl01[4], bl23[4];
        ldsm_x4(ah[0], ah[1], ah[2], ah[3], ahB + kb);
        ldsm_x4(al[0], al[1], al[2], al[3], alB + kb);
        ldsm_x4(bh01[0], bh01[1], bh01[2], bh01[3], bhB + bOff01 + kb);
        ldsm_x4(bh23[0], bh23[1], bh23[2], bh23[3], bhB + bOff23 + kb);
        ldsm_x4(bl01[0], bl01[1], bl01[2], bl01[3], blB + bOff01 + kb);
        ldsm_x4(bl23[0], bl23[1], bl23[2], bl23[3], blB + bOff23 + kb);
#pragma unroll
        for (int g = 0; g < 4; g++) {
            uint32_t b0h = (g < 2) ? bh01[2 * g]     : bh23[2 * (g - 2)];
            uint32_t b1h = (g < 2) ? bh01[2 * g + 1] : bh23[2 * (g - 2) + 1];
            uint32_t b0l = (g < 2) ? bl01[2 * g]     : bl23[2 * (g - 2)];
            uint32_t b1l = (g < 2) ? bl01[2 * g + 1] : bl23[2 * (g - 2) + 1];
            float* d = acc[g];
            mma16816(d[0], d[1], d[2], d[3], ah[0], ah[1], ah[2], ah[3], b0h, b1h);
            mma16816(d[0], d[1], d[2], d[3], ah[0], ah[1], ah[2], ah[3], b0l, b1l);
            mma16816(d[0], d[1], d[2], d[3], al[0], al[1], al[2], al[3], b0h, b1h);
        }
    }
}

template <int PH>
__global__ void __launch_bounds__(256) k_step(int t, float* __restrict__ out2) {
    extern __shared__ char smem[];
    __shared__ float s_sm[B_];
    uint32_t sb = smem_to_u32(smem);
    int tid = threadIdx.x, lane = tid & 31, wid = tid >> 5;
    int hb = blockIdx.x * 8;

    constexpr int A_CH = (PH & 1) ? 16 : 0;
    constexpr int NC = A_CH + ((PH & 2) ? 8 : 0);

    int rb1 = t & 1;                 // h1 read parity (lstm1(t))
    int tp = t - 1;                  // lstm2 step
    int px = tp & 1;                 // x2 parity read by lstm2

    // chunk -> source pointers
    auto srcs = [&](int c, const uint4*& A4h, const uint4*& A4l,
                    const uint4*& W4h, const uint4*& W4l, int& kq) {
        if ((PH & 1) && c < A_CH) {
            if (c < 8) {
                A4h = (const uint4*)g_x2h[px]; A4l = (const uint4*)g_x2l[px];
                W4h = (const uint4*)g_Wih2_h;  W4l = (const uint4*)g_Wih2_l;
                kq = c * 16;
            } else {
                A4h = (const uint4*)g_h2h[px]; A4l = (const uint4*)g_h2l[px];
                W4h = (const uint4*)g_Whh2_h;  W4l = (const uint4*)g_Whh2_l;
                kq = (c - 8) * 16;
            }
        } else {
            A4h = (const uint4*)g_h1h[rb1]; A4l = (const uint4*)g_h1l[rb1];
            W4h = (const uint4*)g_Whh1_h;   W4l = (const uint4*)g_Whh1_l;
            kq = (c - A_CH) * 16;
        }
    };

    float accA[4][4], accB[4][4];
#pragma unroll
    for (int g = 0; g < 4; g++)
#pragma unroll
        for (int c = 0; c < 4; c++) { accA[g][c] = 0.f; accB[g][c] = 0.f; }

    {
        const uint4 *A4h, *A4l, *W4h, *W4l; int kq;
        srcs(0, A4h, A4l, W4h, W4l, kq);
        pf_A(sb, 0, A4h, A4l, kq, tid);
        pf_B(sb, 0, W4h, W4l, hb, kq, tid);
        CP_COMMIT();
    }

    // boundary gate s(t) from partial dots of previous launch (deterministic order)
    if ((PH & 2) && tid < B_) {
        const float* pp = &g_part[rb1][tid][0];
        float u0 = 0.f, u1 = 0.f, u2 = 0.f, u3 = 0.f;
#pragma unroll 8
        for (int c = 0; c < B_; c += 4) {
            u0 += pp[c]; u1 += pp[c + 1]; u2 += pp[c + 2]; u3 += pp[c + 3];
        }
        float u = ((u0 + u1) + (u2 + u3)) + g_abd[tid * T_ + t];
        s_sm[tid] = rintf(sigf(u));
    }

    for (int c = 0; c < NC; c++) {
        int buf = c & 1;
        if (c + 1 < NC) {
            const uint4 *A4h, *A4l, *W4h, *W4l; int kq;
            srcs(c + 1, A4h, A4l, W4h, W4l, kq);
            pf_A(sb, buf ^ 1, A4h, A4l, kq, tid);
            pf_B(sb, buf ^ 1, W4h, W4l, hb, kq, tid);
            CP_COMMIT();
            CP_WAIT1();
        } else {
            CP_WAIT0();
        }
        __syncthreads();
        if ((PH & 1) && c < A_CH) comp_chunk(sb, buf, wid, lane, accA);
        else                       comp_chunk(sb, buf, wid, lane, accB);
        __syncthreads();
    }

    int gr = lane >> 2, tc = lane & 3;
    int h0 = hb + 2 * tc;

    if (PH & 1) {
        // lstm2(t-1) epilogue: h2[px^1], c2
        int wh2 = px ^ 1;
#pragma unroll
        for (int rs = 0; rs < 2; rs++) {
            int b = wid * 16 + gr + 8 * rs;
            int idx = b * H_ + h0;
            float2 coldp = *(const float2*)&g_c2[idx];
            float gi0 = accA[0][2 * rs], gi1 = accA[0][2 * rs + 1];
            float gf0 = accA[1][2 * rs], gf1 = accA[1][2 * rs + 1];
            float gg0 = accA[2][2 * rs], gg1 = accA[2][2 * rs + 1];
            float go0 = accA[3][2 * rs], go1 = accA[3][2 * rs + 1];
            float cn0 = sigf(gf0) * coldp.x + sigf(gi0) * tanhf(gg0);
            float cn1 = sigf(gf1) * coldp.y + sigf(gi1) * tanhf(gg1);
            float hn0 = sigf(go0) * tanhf(cn0);
            float hn1 = sigf(go1) * tanhf(cn1);
            *(float2*)&g_c2[idx] = make_float2(cn0, cn1);
            *(uint32_t*)&g_h2h[wh2][idx] = pack_hi(hn0, hn1);
            *(uint32_t*)&g_h2l[wh2][idx] = pack_lo(hn0, hn1);
            if (out2) *(float2*)&out2[idx] = make_float2(hn0, hn1);
        }
    }

    if (PH & 2) {
        // lstm1(t) epilogue: h1[rb1^1], x2[rb1], c1, gate partial for t+1
        int wb = rb1 ^ 1;
        float2 wv = *(const float2*)&g_wshv[h0];
#pragma unroll
        for (int rs = 0; rs < 2; rs++) {
            int b = wid * 16 + gr + 8 * rs;
            float s = s_sm[b];
            const float* a1 = g_A1 + (size_t)(b * T_ + t) * G4_;
            float2 ai = *(const float2*)&a1[h0];
            float2 af = *(const float2*)&a1[1024 + h0];
            float2 ag = *(const float2*)&a1[2048 + h0];
            float2 ao = *(const float2*)&a1[3072 + h0];
            int idx = b * H_ + h0;
            float2 coldp = *(const float2*)&g_c1[idx];

            float gi0 = accB[0][2 * rs] + ai.x, gi1 = accB[0][2 * rs + 1] + ai.y;
            float gf0 = accB[1][2 * rs] + af.x, gf1 = accB[1][2 * rs + 1] + af.y;
            float gg0 = accB[2][2 * rs] + ag.x, gg1 = accB[2][2 * rs + 1] + ag.y;
            float go0 = accB[3][2 * rs] + ao.x, go1 = accB[3][2 * rs + 1] + ao.y;

            float cn0 = sigf(gf0) * coldp.x + sigf(gi0) * tanhf(gg0);
            float cn1 = sigf(gf1) * coldp.y + sigf(gi1) * tanhf(gg1);
            float hn0 = sigf(go0) * tanhf(cn0);
            float hn1 = sigf(go1) * tanhf(cn1);

            float x20 = hn0 * s,          x21 = hn1 * s;
            float h10 = hn0 * (1.0f - s), h11 = hn1 * (1.0f - s);
            float c10 = cn0 * (1.0f - s), c11 = cn1 * (1.0f - s);

            *(float2*)&g_c1[idx] = make_float2(c10, c11);
            *(uint32_t*)&g_h1h[wb][idx] = pack_hi(h10, h11);
            *(uint32_t*)&g_h1l[wb][idx] = pack_lo(h10, h11);
            *(uint32_t*)&g_x2h[rb1][idx] = pack_hi(x20, x21);
            *(uint32_t*)&g_x2l[rb1][idx] = pack_lo(x20, x21);

            // gate partial: sum this CTA's 8 cols via butterfly over tc (lanes 1,2)
            float pc = h10 * wv.x + h11 * wv.y;
            pc += __shfl_xor_sync(0xffffffffu, pc, 1);
            pc += __shfl_xor_sync(0xffffffffu, pc, 2);
            if (tc == 0) g_part[wb][b][blockIdx.x] = pc;
        }
    }
}

// ---------------- launch ---------------------------------------------------
extern "C" void kernel_launch(void* const* d_in, const int* in_sizes, int n_in,
                              void* d_out, int out_size) {
    const float* video   = (const float*)d_in[0];
    const float* W_embed = (const float*)d_in[1];
    const float* b_embed = (const float*)d_in[2];
    const float* W_ih1   = (const float*)d_in[3];
    const float* W_hh1   = (const float*)d_in[4];
    const float* b1      = (const float*)d_in[5];
    const float* Wsi     = (const float*)d_in[6];
    const float* Wsh     = (const float*)d_in[7];
    const float* b_bd    = (const float*)d_in[8];
    const float* vs      = (const float*)d_in[9];
    const float* W_ih2   = (const float*)d_in[10];
    const float* W_hh2   = (const float*)d_in[11];
    float* out = (float*)d_out;

    bf16 *vidh, *vidl, *Vh, *Vl, *Weh, *Wel, *W1h, *W1l;
    float *pV, *pA1;
    cudaGetSymbolAddress((void**)&vidh, g_vidh);  cudaGetSymbolAddress((void**)&vidl, g_vidl);
    cudaGetSymbolAddress((void**)&Vh, g_Vh);      cudaGetSymbolAddress((void**)&Vl, g_Vl);
    cudaGetSymbolAddress((void**)&Weh, g_Wemb_h); cudaGetSymbolAddress((void**)&Wel, g_Wemb_l);
    cudaGetSymbolAddress((void**)&W1h, g_Wih1_h); cudaGetSymbolAddress((void**)&W1l, g_Wih1_l);
    cudaGetSymbolAddress((void**)&pV, g_V);       cudaGetSymbolAddress((void**)&pA1, g_A1);

    cudaFuncSetAttribute(k_step<1>, cudaFuncAttributeMaxDynamicSharedMemorySize, SMEM_SCAN);
    cudaFuncSetAttribute(k_step<2>, cudaFuncAttributeMaxDynamicSharedMemorySize, SMEM_SCAN);
    cudaFuncSetAttribute(k_step<3>, cudaFuncAttributeMaxDynamicSharedMemorySize, SMEM_SCAN);
    cudaFuncSetAttribute(mm_pre<true, true, true>,
                         cudaFuncAttributeMaxDynamicSharedMemorySize, MM_SMEM);
    cudaFuncSetAttribute(mm_pre<false, true, false>,
                         cudaFuncAttributeMaxDynamicSharedMemorySize, MM_SMEM);

    // 1) boundary-detector projections (fp32)
    k_proj<<<9, 128>>>(Wsi, Wsh, b_bd, vs);

    // 2) fused split of all fp32 operands into (hi, lo) bf16
    k_split_all<<<SPLIT_TOTAL4 / 256, 256>>>(video, W_embed, W_ih1, W_hh1, W_ih2, W_hh2);

    // 3) embed: V = relu(video @ W_embed^T + b), also emit split-bf16 V
    mm_pre<true, true, true><<<dim3(H_ / 128, 64), 256, MM_SMEM>>>(
        vidh, vidl, Weh, Wel, b_embed, pV, Vh, Vl, H_, F_);

    // 4) A1 = V @ W_ih1^T + b1
    mm_pre<false, true, false><<<dim3(G4_ / 128, 64), 256, MM_SMEM>>>(
        Vh, Vl, W1h, W1l, b1, pA1, nullptr, nullptr, G4_, H_);

    // 5) abd + zero state + zero gate partials
    k_abd_init<<<1536 + 64, 256>>>();

    // 6+) fused scan: L_0 = lstm1(0); L_t = lstm2(t-1)+lstm1(t); L_64 = lstm2(63)
    k_step<2><<<128, 256, SMEM_SCAN>>>(0, nullptr);
    for (int t = 1; t < T_; t++)
        k_step<3><<<128, 256, SMEM_SCAN>>>(t, nullptr);
    k_step<1><<<128, 256, SMEM_SCAN>>>(T_, out);
}

// round 16
// speedup vs baseline: 1.0144x; 1.0144x over previous
#include <cuda_runtime.h>
#include <cuda_bf16.h>
#include <stdint.h>
#include <math.h>

#define B_ 128
#define T_ 64
#define F_ 2048
#define H_ 1024
#define M_ 512
#define G4_ 4096

typedef __nv_bfloat16 bf16;

// ---------------- fp32 scratch ---------------------------------------------
__device__ float g_V[B_ * T_ * H_];
__device__ float g_A1[(size_t)B_ * T_ * G4_];
__device__ float g_abd[B_ * T_];
__device__ float g_wsiv[H_], g_wshv[H_];
__device__ float g_bb;
__device__ float g_h1f[2][B_ * H_];
__device__ float g_c1[B_ * H_], g_c2[B_ * H_];
__device__ float g_s[B_];

// ---------------- split-bf16 operands --------------------------------------
__device__ bf16 g_vidh[B_ * T_ * F_], g_vidl[B_ * T_ * F_];
__device__ bf16 g_Vh[B_ * T_ * H_],   g_Vl[B_ * T_ * H_];
__device__ bf16 g_Wemb_h[H_ * F_],    g_Wemb_l[H_ * F_];
__device__ bf16 g_Wih1_h[G4_ * H_],   g_Wih1_l[G4_ * H_];
__device__ bf16 g_Whh1_h[G4_ * H_],   g_Whh1_l[G4_ * H_];
__device__ bf16 g_Wih2_h[G4_ * H_],   g_Wih2_l[G4_ * H_];
__device__ bf16 g_Whh2_h[G4_ * H_],   g_Whh2_l[G4_ * H_];
__device__ bf16 g_h1h[2][B_ * H_],    g_h1l[2][B_ * H_];
__device__ bf16 g_h2h[2][B_ * H_],    g_h2l[2][B_ * H_];
__device__ bf16 g_x2h[B_ * H_],       g_x2l[B_ * H_];

__device__ __forceinline__ float sigf(float x) { return 1.0f / (1.0f + expf(-x)); }
__device__ __forceinline__ uint32_t pack_hi(float x, float y) {
    __nv_bfloat162 t; t.x = __float2bfloat16(x); t.y = __float2bfloat16(y);
    return *(uint32_t*)&t;
}
__device__ __forceinline__ uint32_t pack_lo(float x, float y) {
    bf16 hx = __float2bfloat16(x), hy = __float2bfloat16(y);
    __nv_bfloat162 t;
    t.x = __float2bfloat16(x - __bfloat162float(hx));
    t.y = __float2bfloat16(y - __bfloat162float(hy));
    return *(uint32_t*)&t;
}
__device__ __forceinline__ void mma16816(float& c0, float& c1, float& c2, float& c3,
                                         uint32_t a0, uint32_t a1, uint32_t a2, uint32_t a3,
                                         uint32_t b0, uint32_t b1) {
    asm volatile(
        "mma.sync.aligned.m16n8k16.row.col.f32.bf16.bf16.f32 "
        "{%0,%1,%2,%3},{%4,%5,%6,%7},{%8,%9},{%0,%1,%2,%3};"
        : "+f"(c0), "+f"(c1), "+f"(c2), "+f"(c3)
        : "r"(a0), "r"(a1), "r"(a2), "r"(a3), "r"(b0), "r"(b1));
}
__device__ __forceinline__ void ldsm_x4(uint32_t& r0, uint32_t& r1, uint32_t& r2, uint32_t& r3,
                                        uint32_t addr) {
    asm volatile("ldmatrix.sync.aligned.m8n8.x4.shared.b16 {%0,%1,%2,%3}, [%4];"
                 : "=r"(r0), "=r"(r1), "=r"(r2), "=r"(r3) : "r"(addr));
}
__device__ __forceinline__ uint32_t smem_to_u32(const void* p) {
    uint32_t a;
    asm("{ .reg .u64 t; cvta.to.shared.u64 t, %1; cvt.u32.u64 %0, t; }" : "=r"(a) : "l"(p));
    return a;
}
__device__ __forceinline__ void cpa16(uint32_t dst, const void* src) {
    asm volatile("cp.async.cg.shared.global [%0], [%1], 16;" :: "r"(dst), "l"(src));
}
#define CP_COMMIT() asm volatile("cp.async.commit_group;" ::: "memory")
#define CP_WAIT1()  asm volatile("cp.async.wait_group 1;" ::: "memory")
#define CP_WAIT0()  asm volatile("cp.async.wait_group 0;" ::: "memory")

// ---------------- fused split: all 6 fp32 tensors -> (hi,lo) bf16 -----------
#define SPLIT_TOTAL4 8912896
__global__ void k_split_all(const float* __restrict__ video, const float* __restrict__ W_embed,
                            const float* __restrict__ W_ih1, const float* __restrict__ W_hh1,
                            const float* __restrict__ W_ih2, const float* __restrict__ W_hh2) {
    long i = (long)blockIdx.x * 256 + threadIdx.x;
    const float* src; bf16 *h, *l; long j;
    if (i < 4194304L)       { src = video;   h = g_vidh;   l = g_vidl;   j = i; }
    else if (i < 4718592L)  { src = W_embed; h = g_Wemb_h; l = g_Wemb_l; j = i - 4194304L; }
    else if (i < 5767168L)  { src = W_ih1;   h = g_Wih1_h; l = g_Wih1_l; j = i - 4718592L; }
    else if (i < 6815744L)  { src = W_hh1;   h = g_Whh1_h; l = g_Whh1_l; j = i - 5767168L; }
    else if (i < 7864320L)  { src = W_ih2;   h = g_Wih2_h; l = g_Wih2_l; j = i - 6815744L; }
    else                    { src = W_hh2;   h = g_Whh2_h; l = g_Whh2_l; j = i - 7864320L; }
    float4 v = ((const float4*)src)[j];
    uint2 hp, lp;
    hp.x = pack_hi(v.x, v.y); hp.y = pack_hi(v.z, v.w);
    lp.x = pack_lo(v.x, v.y); lp.y = pack_lo(v.z, v.w);
    ((uint2*)h)[j] = hp;
    ((uint2*)l)[j] = lp;
}

// ---------------- boundary-detector projections ----------------------------
__global__ void k_proj(const float* __restrict__ Wsi, const float* __restrict__ Wsh,
                       const float* __restrict__ b_bd, const float* __restrict__ vs) {
    int blk = blockIdx.x;
    if (blk < 8) {
        int h = blk * 128 + threadIdx.x;
        float s1 = 0.f, s2 = 0.f;
        for (int m = 0; m < M_; m++) {
            float v = vs[m];
            s1 += Wsi[m * H_ + h] * v;
            s2 += Wsh[m * H_ + h] * v;
        }
        g_wsiv[h] = s1;
        g_wshv[h] = s2;
    } else {
        __shared__ float red[128];
        float s = 0.f;
        for (int m = threadIdx.x; m < M_; m += 128) s += b_bd[m] * vs[m];
        red[threadIdx.x] = s;
        __syncthreads();
        for (int st = 64; st > 0; st >>= 1) {
            if (threadIdx.x < st) red[threadIdx.x] += red[threadIdx.x + st];
            __syncthreads();
        }
        if (threadIdx.x == 0) g_bb = red[0];
    }
}

// ========== precompute GEMM: BM128 x BN128 x BK32, warp 64x32, cp.async =====
#define MM_TA    10240
#define MM_BUF   (4 * MM_TA)
#define MM_SMEM  (2 * MM_BUF)

__device__ __forceinline__ void mm_pf(uint32_t sb, int stage,
                                      const uint4* __restrict__ A4h, const uint4* __restrict__ A4l,
                                      const uint4* __restrict__ B4h, const uint4* __restrict__ B4l,
                                      int bm0, int bn0, int kq, int K8, int tid) {
    uint32_t st = sb + stage * MM_BUF;
#pragma unroll
    for (int rep = 0; rep < 2; rep++) {
        int u = tid + 256 * rep;
        int r = u >> 2, q = u & 3;
        uint32_t off = (uint32_t)(r * 80 + q * 16);
        cpa16(st + off,              A4h + (size_t)(bm0 + r) * K8 + kq + q);
        cpa16(st + MM_TA + off,      A4l + (size_t)(bm0 + r) * K8 + kq + q);
        cpa16(st + 2 * MM_TA + off,  B4h + (size_t)(bn0 + r) * K8 + kq + q);
        cpa16(st + 3 * MM_TA + off,  B4l + (size_t)(bn0 + r) * K8 + kq + q);
    }
}

__device__ __forceinline__ void mm_comp(uint32_t sb, int stage, uint32_t aOff, uint32_t bOff,
                                        float acc[4][4][4]) {
    uint32_t st = sb + stage * MM_BUF;
    uint32_t sAH = st, sAL = st + MM_TA, sBH = st + 2 * MM_TA, sBL = st + 3 * MM_TA;
#pragma unroll
    for (int ks = 0; ks < 32; ks += 16) {
        uint32_t kb = (uint32_t)(ks * 2);
        uint32_t bh[2][4], bl[2][4];
#pragma unroll
        for (int p = 0; p < 2; p++) {
            ldsm_x4(bh[p][0], bh[p][1], bh[p][2], bh[p][3], sBH + bOff + p * 1280 + kb);
            ldsm_x4(bl[p][0], bl[p][1], bl[p][2], bl[p][3], sBL + bOff + p * 1280 + kb);
        }
#pragma unroll
        for (int mt = 0; mt < 4; mt++) {
            uint32_t ah[4], al[4];
            ldsm_x4(ah[0], ah[1], ah[2], ah[3], sAH + aOff + mt * 1280 + kb);
            ldsm_x4(al[0], al[1], al[2], al[3], sAL + aOff + mt * 1280 + kb);
#pragma unroll
            for (int nt = 0; nt < 4; nt++) {
                int p = nt >> 1, j = nt & 1;
                float* d = acc[mt][nt];
                mma16816(d[0], d[1], d[2], d[3], ah[0], ah[1], ah[2], ah[3], bh[p][2 * j], bh[p][2 * j + 1]);
                mma16816(d[0], d[1], d[2], d[3], ah[0], ah[1], ah[2], ah[3], bl[p][2 * j], bl[p][2 * j + 1]);
                mma16816(d[0], d[1], d[2], d[3], al[0], al[1], al[2], al[3], bh[p][2 * j], bh[p][2 * j + 1]);
            }
        }
    }
}

template <bool RELU, bool BIAS, bool SPLIT>
__global__ void __launch_bounds__(256) mm_pre(const bf16* __restrict__ Ah, const bf16* __restrict__ Al,
                       const bf16* __restrict__ Bh, const bf16* __restrict__ Bl,
                       const float* __restrict__ bias, float* __restrict__ C,
                       bf16* __restrict__ Ch, bf16* __restrict__ Cl, int N, int K) {
    extern __shared__ char smp[];
    uint32_t sb = smem_to_u32(smp);
    int tid = threadIdx.x, lane = tid & 31, wid = tid >> 5;
    int wm = wid >> 2, wn = wid & 3;
    int gr = lane >> 2, tc = lane & 3;
    int bn0 = blockIdx.x * 128, bm0 = blockIdx.y * 128;
    int K8 = K >> 3;
    const uint4* A4h = (const uint4*)Ah; const uint4* A4l = (const uint4*)Al;
    const uint4* B4h = (const uint4*)Bh; const uint4* B4l = (const uint4*)Bl;

    uint32_t aOff = (uint32_t)((wm * 64 + (lane & 15)) * 80 + (lane >> 4) * 16);
    uint32_t bOff = (uint32_t)((wn * 32 + ((lane >> 4) & 1) * 8 + (lane & 7)) * 80
                               + ((lane >> 3) & 1) * 16);

    float acc[4][4][4];
#pragma unroll
    for (int a = 0; a < 4; a++)
#pragma unroll
        for (int b = 0; b < 4; b++)
#pragma unroll
            for (int c = 0; c < 4; c++) acc[a][b][c] = 0.f;

    int nc = K >> 5;
    mm_pf(sb, 0, A4h, A4l, B4h, B4l, bm0, bn0, 0, K8, tid);
    CP_COMMIT();
    for (int c = 0; c < nc; c++) {
        int stg = c & 1;
        if (c + 1 < nc) {
            mm_pf(sb, stg ^ 1, A4h, A4l, B4h, B4l, bm0, bn0, (c + 1) * 4, K8, tid);
            CP_COMMIT();
            CP_WAIT1();
        } else {
            CP_WAIT0();
        }
        __syncthreads();
        mm_comp(sb, stg, aOff, bOff, acc);
        __syncthreads();
    }

#pragma unroll
    for (int mt = 0; mt < 4; mt++)
#pragma unroll
        for (int nt = 0; nt < 4; nt++) {
            int row0 = bm0 + wm * 64 + mt * 16 + gr;
            int col = bn0 + wn * 32 + nt * 8 + 2 * tc;
            float2 bs = BIAS ? *(const float2*)&bias[col] : make_float2(0.f, 0.f);
#pragma unroll
            for (int rs = 0; rs < 2; rs++) {
                int row = row0 + 8 * rs;
                float v0 = acc[mt][nt][2 * rs] + bs.x;
                float v1 = acc[mt][nt][2 * rs + 1] + bs.y;
                if (RELU) { v0 = fmaxf(v0, 0.f); v1 = fmaxf(v1, 0.f); }
                *(float2*)&C[(size_t)row * N + col] = make_float2(v0, v1);
                if (SPLIT) {
                    *(uint32_t*)&Ch[(size_t)row * N + col] = pack_hi(v0, v1);
                    *(uint32_t*)&Cl[(size_t)row * N + col] = pack_lo(v0, v1);
                }
            }
        }
}

// ---------------- fused abd + t0-gate + state init -------------------------
__global__ void k_abd_init() {
    if (blockIdx.x < 1024) {
        int r = blockIdx.x * 8 + (threadIdx.x >> 5);
        int lane = threadIdx.x & 31;
        const float* vr = g_V + (size_t)r * H_;
        float s = 0.f;
        for (int h = lane; h < H_; h += 32) s += vr[h] * g_wsiv[h];
#pragma unroll
        for (int o = 16; o > 0; o >>= 1) s += __shfl_xor_sync(0xffffffffu, s, o);
        if (lane == 0) {
            float u = s + g_bb;
            g_abd[r] = u;
            if ((r & (T_ - 1)) == 0)
                g_s[r >> 6] = rintf(sigf(u));
        }
    } else {
        int i = (blockIdx.x - 1024) * 256 + threadIdx.x;
        if (i < B_ * H_) {
            g_c1[i] = 0.f; g_c2[i] = 0.f;
            bf16 z = __float2bfloat16(0.f);
            g_h1h[0][i] = z; g_h1l[0][i] = z;
            g_h2h[0][i] = z; g_h2l[0][i] = z;
        }
    }
}

// ================= scan kernels: CTA = 64 batch x 64 gate-cols ==============
// grid 128 = 2 m-slices x 64 n-slices. Warps 2m x 4n, warp tile 32m x 16n.
// Weight rows interleaved in smem: smem row n <-> global row (n&3)*H + hid,
// hid = hb16 + (n>>2). Each warp owns 4 hid cols with all 4 gates.
#define A_ST   136
#define TSB    (A_ST * 2)                        // 272 B per smem row
#define SA_TILE (64 * TSB)                       // 17408 B
#define SBUF    (4 * SA_TILE)                    // AH AL BH BL = 69632 B
#define SM2_AH(b) ((b) * SBUF)
#define SM2_AL(b) ((b) * SBUF + SA_TILE)
#define SM2_BH(b) ((b) * SBUF + 2 * SA_TILE)
#define SM2_BL(b) ((b) * SBUF + 3 * SA_TILE)
#define SMEM_SCAN (2 * SBUF)                     // 139264 B

// prefetch A: 64 batch rows x 128 K (hi+lo); global row = bm0 + r
__device__ __forceinline__ void pf_A(uint32_t sb, int buf,
                                     const uint4* __restrict__ Ah4,
                                     const uint4* __restrict__ Al4,
                                     int bm0, int kq, int tid) {
#pragma unroll
    for (int rep = 0; rep < 4; rep++) {
        int u = tid + 256 * rep;
        int r = u >> 4, q = u & 15;
        uint32_t off = (uint32_t)(r * TSB + q * 16);
        cpa16(sb + SM2_AH(buf) + off, Ah4 + (size_t)(bm0 + r) * 128 + kq + q);
        cpa16(sb + SM2_AL(buf) + off, Al4 + (size_t)(bm0 + r) * 128 + kq + q);
    }
}
// prefetch B: 64 interleaved weight rows x 128 K (hi+lo)
__device__ __forceinline__ void pf_B(uint32_t sb, int buf,
                                     const uint4* __restrict__ Wh4,
                                     const uint4* __restrict__ Wl4,
                                     int hb16, int kq, int tid) {
#pragma unroll
    for (int rep = 0; rep < 4; rep++) {
        int u = tid + 256 * rep;
        int n = u >> 4, q = u & 15;
        int wr = (n & 3) * H_ + hb16 + (n >> 2);
        uint32_t off = (uint32_t)(n * TSB + q * 16);
        cpa16(sb + SM2_BH(buf) + off, Wh4 + (size_t)wr * 128 + kq + q);
        cpa16(sb + SM2_BL(buf) + off, Wl4 + (size_t)wr * 128 + kq + q);
    }
}
// one K=128 chunk: warp tile 32m x 16n; acc[2][2][4]
__device__ __forceinline__ void comp_chunk(uint32_t sb, int buf, int wm, int wn, int lane,
                                           float acc[2][2][4]) {
    uint32_t aOff = (uint32_t)((wm * 32 + (lane & 15)) * TSB + (lane >> 4) * 16);
    uint32_t bOff = (uint32_t)((wn * 16 + ((lane >> 4) & 1) * 8 + (lane & 7)) * TSB
                               + ((lane >> 3) & 1) * 16);
    uint32_t sAH = sb + SM2_AH(buf), sAL = sb + SM2_AL(buf);
    uint32_t sBH = sb + SM2_BH(buf), sBL = sb + SM2_BL(buf);
#pragma unroll
    for (int ks = 0; ks < 128; ks += 16) {
        uint32_t kb = (uint32_t)(ks * 2);
        uint32_t bh[4], bl[4];
        ldsm_x4(bh[0], bh[1], bh[2], bh[3], sBH + bOff + kb);
        ldsm_x4(bl[0], bl[1], bl[2], bl[3], sBL + bOff + kb);
#pragma unroll
        for (int mt = 0; mt < 2; mt++) {
            uint32_t ah[4], al[4];
            ldsm_x4(ah[0], ah[1], ah[2], ah[3], sAH + aOff + mt * (16 * TSB) + kb);
            ldsm_x4(al[0], al[1], al[2], al[3], sAL + aOff + mt * (16 * TSB) + kb);
#pragma unroll
            for (int nt = 0; nt < 2; nt++) {
                float* d = acc[mt][nt];
                mma16816(d[0], d[1], d[2], d[3], ah[0], ah[1], ah[2], ah[3], bh[2 * nt], bh[2 * nt + 1]);
                mma16816(d[0], d[1], d[2], d[3], ah[0], ah[1], ah[2], ah[3], bl[2 * nt], bl[2 * nt + 1]);
                mma16816(d[0], d[1], d[2], d[3], al[0], al[1], al[2], al[3], bh[2 * nt], bh[2 * nt + 1]);
            }
        }
    }
}

// scan step 1: gates1 = h1 @ Whh1^T + A1 -> LSTM1 + boundary mask. grid=128
__global__ void __launch_bounds__(256) k_lstm1(int t, int rb) {
    extern __shared__ char smem[];
    uint32_t sb = smem_to_u32(smem);
    int tid = threadIdx.x, lane = tid & 31, wid = tid >> 5;
    int wm = wid >> 2, wn = wid & 3;
    int nsl = blockIdx.x & 63, msl = blockIdx.x >> 6;
    int hb16 = nsl * 16, bm0 = msl * 64;
    const uint4* Ah4 = (const uint4*)g_h1h[rb];
    const uint4* Al4 = (const uint4*)g_h1l[rb];
    const uint4* Wh4 = (const uint4*)g_Whh1_h;
    const uint4* Wl4 = (const uint4*)g_Whh1_l;

    float acc[2][2][4];
#pragma unroll
    for (int a = 0; a < 2; a++)
#pragma unroll
        for (int b = 0; b < 2; b++)
#pragma unroll
            for (int c = 0; c < 4; c++) acc[a][b][c] = 0.f;

    pf_A(sb, 0, Ah4, Al4, bm0, 0, tid);
    pf_B(sb, 0, Wh4, Wl4, hb16, 0, tid);
    CP_COMMIT();
    for (int c = 0; c < 8; c++) {
        int buf = c & 1;
        if (c + 1 < 8) {
            pf_A(sb, buf ^ 1, Ah4, Al4, bm0, (c + 1) * 16, tid);
            pf_B(sb, buf ^ 1, Wh4, Wl4, hb16, (c + 1) * 16, tid);
            CP_COMMIT();
            CP_WAIT1();
        } else {
            CP_WAIT0();
        }
        __syncthreads();
        comp_chunk(sb, buf, wm, wn, lane, acc);
        __syncthreads();
    }

    // epilogue: lanes pair via shfl_xor(1); tc even owns one hid col.
    int wb = rb ^ 1;
    int gr = lane >> 2, tc = lane & 3;
    bool owner = (tc & 1) == 0;
    int hsel = tc >> 1;
#pragma unroll
    for (int mt = 0; mt < 2; mt++)
#pragma unroll
        for (int nt = 0; nt < 2; nt++) {
            int h = hb16 + wn * 4 + nt * 2 + hsel;
#pragma unroll
            for (int rs = 0; rs < 2; rs++) {
                float v0 = acc[mt][nt][2 * rs], v1 = acc[mt][nt][2 * rs + 1];
                float p0 = __shfl_xor_sync(0xffffffffu, v0, 1);
                float p1 = __shfl_xor_sync(0xffffffffu, v1, 1);
                if (owner) {
                    int b = bm0 + wm * 32 + mt * 16 + gr + 8 * rs;
                    float s = g_s[b];
                    const float* a1 = g_A1 + (size_t)(b * T_ + t) * G4_;
                    float gi = v0 + a1[h];
                    float gf = v1 + a1[1024 + h];
                    float gg = p0 + a1[2048 + h];
                    float go = p1 + a1[3072 + h];
                    int idx = b * H_ + h;
                    float cn = sigf(gf) * g_c1[idx] + sigf(gi) * tanhf(gg);
                    float hn = sigf(go) * tanhf(cn);
                    float x2 = hn * s, h1v = hn * (1.0f - s), c1v = cn * (1.0f - s);
                    g_c1[idx] = c1v;
                    g_h1f[wb][idx] = h1v;
                    bf16 hh = __float2bfloat16(h1v);
                    g_h1h[wb][idx] = hh;
                    g_h1l[wb][idx] = __float2bfloat16(h1v - __bfloat162float(hh));
                    bf16 xh = __float2bfloat16(x2);
                    g_x2h[idx] = xh;
                    g_x2l[idx] = __float2bfloat16(x2 - __bfloat162float(xh));
                }
            }
        }
}

// scan step 2: gates2 = x2 @ Wih2^T + h2 @ Whh2^T (K=2048) -> LSTM2.
// grid = 144: [0,128) GEMM+LSTM2; [128,144) boundary gate for t+1 (fp32).
__global__ void __launch_bounds__(256) k_lstm2(int t, int rb, float* __restrict__ out2) {
    if (blockIdx.x >= 128) {
        if (t + 1 >= T_) return;
        int b = (blockIdx.x - 128) * 8 + (threadIdx.x >> 5);
        int lane = threadIdx.x & 31;
        const float* h1 = g_h1f[rb ^ 1] + (size_t)b * H_;
        float u = 0.f;
        for (int h = lane; h < H_; h += 32) u += h1[h] * g_wshv[h];
#pragma unroll
        for (int o = 16; o > 0; o >>= 1) u += __shfl_xor_sync(0xffffffffu, u, o);
        if (lane == 0) {
            u += g_abd[b * T_ + t + 1];
            g_s[b] = rintf(sigf(u));
        }
        return;
    }

    extern __shared__ char smem[];
    uint32_t sb = smem_to_u32(smem);
    int tid = threadIdx.x, lane = tid & 31, wid = tid >> 5;
    int wm = wid >> 2, wn = wid & 3;
    int nsl = blockIdx.x & 63, msl = blockIdx.x >> 6;
    int hb16 = nsl * 16, bm0 = msl * 64;

    float acc[2][2][4];
#pragma unroll
    for (int a = 0; a < 2; a++)
#pragma unroll
        for (int b = 0; b < 2; b++)
#pragma unroll
            for (int c = 0; c < 4; c++) acc[a][b][c] = 0.f;

    auto pf_chunk = [&](int c, int buf) {
        bool first = (c < 8);
        const uint4* Ah4 = first ? (const uint4*)g_x2h : (const uint4*)g_h2h[rb];
        const uint4* Al4 = first ? (const uint4*)g_x2l : (const uint4*)g_h2l[rb];
        const uint4* Wh4 = first ? (const uint4*)g_Wih2_h : (const uint4*)g_Whh2_h;
        const uint4* Wl4 = first ? (const uint4*)g_Wih2_l : (const uint4*)g_Whh2_l;
        int kq = (c & 7) * 16;
        pf_A(sb, buf, Ah4, Al4, bm0, kq, tid);
        pf_B(sb, buf, Wh4, Wl4, hb16, kq, tid);
    };

    pf_chunk(0, 0);
    CP_COMMIT();
    for (int c = 0; c < 16; c++) {
        int buf = c & 1;
        if (c + 1 < 16) {
            pf_chunk(c + 1, buf ^ 1);
            CP_COMMIT();
            CP_WAIT1();
        } else {
            CP_WAIT0();
        }
        __syncthreads();
        comp_chunk(sb, buf, wm, wn, lane, acc);
        __syncthreads();
    }

    int wh2 = rb ^ 1;
    int gr = lane >> 2, tc = lane & 3;
    bool owner = (tc & 1) == 0;
    int hsel = tc >> 1;
#pragma unroll
    for (int mt = 0; mt < 2; mt++)
#pragma unroll
        for (int nt = 0; nt < 2; nt++) {
            int h = hb16 + wn * 4 + nt * 2 + hsel;
#pragma unroll
            for (int rs = 0; rs < 2; rs++) {
                float v0 = acc[mt][nt][2 * rs], v1 = acc[mt][nt][2 * rs + 1];
                float p0 = __shfl_xor_sync(0xffffffffu, v0, 1);
                float p1 = __shfl_xor_sync(0xffffffffu, v1, 1);
                if (owner) {
                    int b = bm0 + wm * 32 + mt * 16 + gr + 8 * rs;
                    int idx = b * H_ + h;
                    float cn = sigf(v1) * g_c2[idx] + sigf(v0) * tanhf(p0);
                    float hn = sigf(p1) * tanhf(cn);
                    g_c2[idx] = cn;
                    bf16 hh = __float2bfloat16(hn);
                    g_h2h[wh2][idx] = hh;
                    g_h2l[wh2][idx] = __float2bfloat16(hn - __bfloat162float(hh));
                    if (out2) out2[idx] = hn;
                }
            }
        }
}

// ---------------- launch ---------------------------------------------------
extern "C" void kernel_launch(void* const* d_in, const int* in_sizes, int n_in,
                              void* d_out, int out_size) {
    const float* video   = (const float*)d_in[0];
    const float* W_embed = (const float*)d_in[1];
    const float* b_embed = (const float*)d_in[2];
    const float* W_ih1   = (const float*)d_in[3];
    const float* W_hh1   = (const float*)d_in[4];
    const float* b1      = (const float*)d_in[5];
    const float* Wsi     = (const float*)d_in[6];
    const float* Wsh     = (const float*)d_in[7];
    const float* b_bd    = (const float*)d_in[8];
    const float* vs      = (const float*)d_in[9];
    const float* W_ih2   = (const float*)d_in[10];
    const float* W_hh2   = (const float*)d_in[11];
    float* out = (float*)d_out;

    bf16 *vidh, *vidl, *Vh, *Vl, *Weh, *Wel, *W1h, *W1l;
    float *pV, *pA1;
    cudaGetSymbolAddress((void**)&vidh, g_vidh);  cudaGetSymbolAddress((void**)&vidl, g_vidl);
    cudaGetSymbolAddress((void**)&Vh, g_Vh);      cudaGetSymbolAddress((void**)&Vl, g_Vl);
    cudaGetSymbolAddress((void**)&Weh, g_Wemb_h); cudaGetSymbolAddress((void**)&Wel, g_Wemb_l);
    cudaGetSymbolAddress((void**)&W1h, g_Wih1_h); cudaGetSymbolAddress((void**)&W1l, g_Wih1_l);
    cudaGetSymbolAddress((void**)&pV, g_V);       cudaGetSymbolAddress((void**)&pA1, g_A1);

    cudaFuncSetAttribute(k_lstm1, cudaFuncAttributeMaxDynamicSharedMemorySize, SMEM_SCAN);
    cudaFuncSetAttribute(k_lstm2, cudaFuncAttributeMaxDynamicSharedMemorySize, SMEM_SCAN);
    cudaFuncSetAttribute(mm_pre<true, true, true>,
                         cudaFuncAttributeMaxDynamicSharedMemorySize, MM_SMEM);
    cudaFuncSetAttribute(mm_pre<false, true, false>,
                         cudaFuncAttributeMaxDynamicSharedMemorySize, MM_SMEM);

    // 1) boundary-detector projections (fp32)
    k_proj<<<9, 128>>>(Wsi, Wsh, b_bd, vs);

    // 2) fused split of all fp32 operands into (hi, lo) bf16
    k_split_all<<<SPLIT_TOTAL4 / 256, 256>>>(video, W_embed, W_ih1, W_hh1, W_ih2, W_hh2);

    // 3) embed: V = relu(video @ W_embed^T + b), also emit split-bf16 V
    mm_pre<true, true, true><<<dim3(H_ / 128, 64), 256, MM_SMEM>>>(
        vidh, vidl, Weh, Wel, b_embed, pV, Vh, Vl, H_, F_);

    // 4) A1 = V @ W_ih1^T + b1
    mm_pre<false, true, false><<<dim3(G4_ / 128, 64), 256, MM_SMEM>>>(
        Vh, Vl, W1h, W1l, b1, pA1, nullptr, nullptr, G4_, H_);

    // 5) abd + t0 gate + zero state
    k_abd_init<<<1536, 256>>>();

    // 6+) sequential scan (64x64 CTAs, cp.async pipelined HMMA + ldmatrix)
    for (int t = 0; t < T_; t++) {
        int rb = t & 1;
        k_lstm1<<<128, 256, SMEM_SCAN>>>(t, rb);
        k_lstm2<<<144, 256, SMEM_SCAN>>>(t, rb, (t == T_ - 1) ? out : nullptr);
    }
}